// round 1
// baseline (speedup 1.0000x reference)
#include <cuda_runtime.h>

#define NN 50000
#define EE 800000
#define RR 8
#define DD 128

// Scratch (module-load-time device globals; no runtime allocation)
__device__ float g_h[(size_t)RR * NN * DD];   // per-relation transformed nodes: 204.8 MB
__device__ float g_agg[(size_t)NN * DD];      // scatter-add accumulator: 25.6 MB
__device__ int   g_deg[NN];                   // in-degree per dst

// ---------------------------------------------------------------------------
// Kernel 1: zero agg + deg
// ---------------------------------------------------------------------------
__global__ void zero_kernel() {
    size_t i = (size_t)blockIdx.x * blockDim.x + threadIdx.x;
    size_t tot = (size_t)NN * DD;
    if (i < tot) g_agg[i] = 0.0f;
    if (i < NN)  g_deg[i] = 0;
}

// ---------------------------------------------------------------------------
// Kernel 2: per-relation GEMM  h[r] = x @ W_rel[r]
//   x:     [NN, 128] row-major
//   W_rel: [RR, 128, 128] row-major (K x N per relation — no transpose needed)
// Classic 128x128 block tile, BK=8, 256 threads, 8x8 micro-tile per thread.
// ---------------------------------------------------------------------------
__global__ __launch_bounds__(256) void gemm_rel(const float* __restrict__ x,
                                                const float* __restrict__ Wrel) {
    const int r  = blockIdx.y;
    const int m0 = blockIdx.x * 128;
    const float* B = Wrel + (size_t)r * DD * DD;

    __shared__ float As[8][128];
    __shared__ float Bs[8][128];

    const int tid  = threadIdx.x;
    const int arow = tid >> 1;            // 0..127
    const int acol = (tid & 1) * 4;       // 0 or 4
    const int brow = tid >> 5;            // 0..7
    const int bcol = (tid & 31) * 4;      // 0..124
    const int tr   = (tid >> 4) * 8;      // row offset of micro-tile
    const int tc   = (tid & 15) * 8;      // col offset of micro-tile

    const bool arow_ok = (m0 + arow) < NN;
    const float* Aptr = x + (size_t)(m0 + arow) * DD + acol;

    float acc[8][8];
    #pragma unroll
    for (int i = 0; i < 8; i++)
        #pragma unroll
        for (int j = 0; j < 8; j++) acc[i][j] = 0.0f;

    for (int k0 = 0; k0 < DD; k0 += 8) {
        float4 av = arow_ok ? *(const float4*)(Aptr + k0) : make_float4(0, 0, 0, 0);
        As[acol + 0][arow] = av.x;
        As[acol + 1][arow] = av.y;
        As[acol + 2][arow] = av.z;
        As[acol + 3][arow] = av.w;

        float4 bv = *(const float4*)(B + (size_t)(k0 + brow) * DD + bcol);
        *(float4*)&Bs[brow][bcol] = bv;
        __syncthreads();

        #pragma unroll
        for (int kk = 0; kk < 8; kk++) {
            float ar[8], br[8];
            *(float4*)(ar)     = *(const float4*)&As[kk][tr];
            *(float4*)(ar + 4) = *(const float4*)&As[kk][tr + 4];
            *(float4*)(br)     = *(const float4*)&Bs[kk][tc];
            *(float4*)(br + 4) = *(const float4*)&Bs[kk][tc + 4];
            #pragma unroll
            for (int i = 0; i < 8; i++)
                #pragma unroll
                for (int j = 0; j < 8; j++)
                    acc[i][j] = fmaf(ar[i], br[j], acc[i][j]);
        }
        __syncthreads();
    }

    #pragma unroll
    for (int i = 0; i < 8; i++) {
        int m = m0 + tr + i;
        if (m < NN) {
            float* Crow = g_h + ((size_t)r * NN + m) * DD + tc;
            *(float4*)(Crow)     = make_float4(acc[i][0], acc[i][1], acc[i][2], acc[i][3]);
            *(float4*)(Crow + 4) = make_float4(acc[i][4], acc[i][5], acc[i][6], acc[i][7]);
        }
    }
}

// ---------------------------------------------------------------------------
// Kernel 3: edge gather + scatter-add. One warp per edge.
//   Each lane reads one float4 of h[rel][src] (32 lanes x 16B = 512B row)
//   and atomically adds into agg[dst].
// ---------------------------------------------------------------------------
__global__ __launch_bounds__(256) void edge_kernel(const int* __restrict__ ei,
                                                   const int* __restrict__ et) {
    int widx = (int)(((size_t)blockIdx.x * blockDim.x + threadIdx.x) >> 5);
    int lane = threadIdx.x & 31;
    if (widx >= EE) return;

    int s = __ldg(ei + widx);        // src
    int d = __ldg(ei + EE + widx);   // dst
    int r = __ldg(et + widx);        // relation

    const float4* hrow = (const float4*)(g_h + ((size_t)r * NN + s) * DD);
    float4 v = __ldg(hrow + lane);

    float* a = g_agg + (size_t)d * DD + lane * 4;
    atomicAdd(a + 0, v.x);
    atomicAdd(a + 1, v.y);
    atomicAdd(a + 2, v.z);
    atomicAdd(a + 3, v.w);

    if (lane == 0) atomicAdd(&g_deg[d], 1);
}

// ---------------------------------------------------------------------------
// Kernel 4: self-loop GEMM + epilogue
//   out = relu(x @ W_self^T + b + agg / max(deg,1))
//   W_self: [D_OUT=128, D_IN=128] row-major -> B_logical[k][n] = W[n*128 + k]
// ---------------------------------------------------------------------------
__global__ __launch_bounds__(256) void self_epilogue(const float* __restrict__ x,
                                                     const float* __restrict__ Wself,
                                                     const float* __restrict__ bias,
                                                     float* __restrict__ out) {
    const int m0 = blockIdx.x * 128;

    __shared__ float As[8][128];
    __shared__ float Bs[8][128];

    const int tid  = threadIdx.x;
    const int arow = tid >> 1;
    const int acol = (tid & 1) * 4;
    const int nrow = tid >> 1;           // W row (output feature n)
    const int kq   = (tid & 1) * 4;      // k offset within BK chunk
    const int tr   = (tid >> 4) * 8;
    const int tc   = (tid & 15) * 8;

    const bool arow_ok = (m0 + arow) < NN;
    const float* Aptr = x + (size_t)(m0 + arow) * DD + acol;

    float acc[8][8];
    #pragma unroll
    for (int i = 0; i < 8; i++)
        #pragma unroll
        for (int j = 0; j < 8; j++) acc[i][j] = 0.0f;

    for (int k0 = 0; k0 < DD; k0 += 8) {
        float4 av = arow_ok ? *(const float4*)(Aptr + k0) : make_float4(0, 0, 0, 0);
        As[acol + 0][arow] = av.x;
        As[acol + 1][arow] = av.y;
        As[acol + 2][arow] = av.z;
        As[acol + 3][arow] = av.w;

        // transpose-load W_self: Bs[k][n] = W[n*128 + k]
        float4 wv = *(const float4*)(Wself + (size_t)nrow * DD + k0 + kq);
        Bs[kq + 0][nrow] = wv.x;
        Bs[kq + 1][nrow] = wv.y;
        Bs[kq + 2][nrow] = wv.z;
        Bs[kq + 3][nrow] = wv.w;
        __syncthreads();

        #pragma unroll
        for (int kk = 0; kk < 8; kk++) {
            float ar[8], br[8];
            *(float4*)(ar)     = *(const float4*)&As[kk][tr];
            *(float4*)(ar + 4) = *(const float4*)&As[kk][tr + 4];
            *(float4*)(br)     = *(const float4*)&Bs[kk][tc];
            *(float4*)(br + 4) = *(const float4*)&Bs[kk][tc + 4];
            #pragma unroll
            for (int i = 0; i < 8; i++)
                #pragma unroll
                for (int j = 0; j < 8; j++)
                    acc[i][j] = fmaf(ar[i], br[j], acc[i][j]);
        }
        __syncthreads();
    }

    float bj[8];
    #pragma unroll
    for (int j = 0; j < 8; j++) bj[j] = __ldg(bias + tc + j);

    #pragma unroll
    for (int i = 0; i < 8; i++) {
        int m = m0 + tr + i;
        if (m < NN) {
            int dg = g_deg[m];
            float inv = 1.0f / (float)(dg > 1 ? dg : 1);
            const float* arow_agg = g_agg + (size_t)m * DD + tc;
            float* orow = out + (size_t)m * DD + tc;
            float v[8];
            #pragma unroll
            for (int j = 0; j < 8; j++) {
                float t = acc[i][j] + bj[j] + arow_agg[j] * inv;
                v[j] = t > 0.0f ? t : 0.0f;
            }
            *(float4*)(orow)     = make_float4(v[0], v[1], v[2], v[3]);
            *(float4*)(orow + 4) = make_float4(v[4], v[5], v[6], v[7]);
        }
    }
}

// ---------------------------------------------------------------------------
extern "C" void kernel_launch(void* const* d_in, const int* in_sizes, int n_in,
                              void* d_out, int out_size) {
    const float* x     = (const float*)d_in[0];
    const float* Wrel  = (const float*)d_in[1];
    const float* Wself = (const float*)d_in[2];
    const float* bias  = (const float*)d_in[3];
    const int*   ei    = (const int*)d_in[4];   // [2, E]: src then dst
    const int*   et    = (const int*)d_in[5];   // [E]
    float* out = (float*)d_out;

    (void)in_sizes; (void)n_in; (void)out_size;

    zero_kernel<<<(NN * DD + 255) / 256, 256>>>();

    dim3 grel((NN + 127) / 128, RR);
    gemm_rel<<<grel, 256>>>(x, Wrel);

    edge_kernel<<<(int)(((size_t)EE * 32 + 255) / 256), 256>>>(ei, et);

    self_epilogue<<<(NN + 127) / 128, 256>>>(x, Wself, bias, out);
}

// round 3
// speedup vs baseline: 2.0976x; 2.0976x over previous
#include <cuda_runtime.h>
#include <cuda_bf16.h>
#include <cstdint>

#define NN 50000
#define EE 800000
#define RR 8
#define DD 128
#define NREL 9              // 8 relations + self-loop as relation 8
#define MTILES 391          // ceil(50000/128)

// ---------------------------------------------------------------------------
// Device scratch (no runtime allocation allowed)
// ---------------------------------------------------------------------------
__device__ float g_h[(size_t)NREL * NN * DD];   // 230.4 MB
__device__ float g_agg[(size_t)NN * DD];        // 25.6 MB
__device__ int   g_deg[NN];
// Pre-split weights, bf16 hi/lo, already in the swizzled [row][chunk] smem image
__device__ uint4 g_WbHi[NREL * 2048];           // 32 KB / relation
__device__ uint4 g_WbLo[NREL * 2048];

// ---------------------------------------------------------------------------
__device__ __forceinline__ uint32_t smem_u32(const void* p) {
    return (uint32_t)__cvta_generic_to_shared(p);
}
// row in [0,128), cc = 16B-chunk in [0,16). XOR swizzle on low 3 chunk bits.
__device__ __forceinline__ int chidx(int row, int cc) {
    return row * 16 + ((cc & 8) | ((cc ^ row) & 7));
}

__device__ __forceinline__ void ldsm_x4(uint32_t* d, uint32_t addr) {
    asm volatile("ldmatrix.sync.aligned.m8n8.x4.shared.b16 {%0,%1,%2,%3}, [%4];"
                 : "=r"(d[0]), "=r"(d[1]), "=r"(d[2]), "=r"(d[3]) : "r"(addr));
}
__device__ __forceinline__ void ldsm_x2(uint32_t* d, uint32_t addr) {
    asm volatile("ldmatrix.sync.aligned.m8n8.x2.shared.b16 {%0,%1}, [%2];"
                 : "=r"(d[0]), "=r"(d[1]) : "r"(addr));
}
__device__ __forceinline__ void mma16816(float* c, const uint32_t* a, const uint32_t* b) {
    asm volatile("mma.sync.aligned.m16n8k16.row.col.f32.bf16.bf16.f32 "
                 "{%0,%1,%2,%3}, {%4,%5,%6,%7}, {%8,%9}, {%0,%1,%2,%3};"
                 : "+f"(c[0]), "+f"(c[1]), "+f"(c[2]), "+f"(c[3])
                 : "r"(a[0]), "r"(a[1]), "r"(a[2]), "r"(a[3]), "r"(b[0]), "r"(b[1]));
}

// ---------------------------------------------------------------------------
// Kernel 1: zero agg + deg
// ---------------------------------------------------------------------------
__global__ void zero_kernel() {
    size_t i = (size_t)blockIdx.x * blockDim.x + threadIdx.x;
    if (i < (size_t)NN * DD) g_agg[i] = 0.0f;
    if (i < NN) g_deg[i] = 0;
}

// ---------------------------------------------------------------------------
// Kernel 2: pack weights -> bf16 hi/lo, swizzled [n-row][k-chunk] layout.
//   B[n][k]:  r<8:  W_rel[r][k][n]   (h = x @ W_rel[r])
//             r==8: W_self_w[n][k]   (x @ W_self^T)
// ---------------------------------------------------------------------------
__global__ void prep_w(const float* __restrict__ Wrel, const float* __restrict__ Wself) {
    int idx = blockIdx.x * 256 + threadIdx.x;
    if (idx >= NREL * DD * DD) return;
    int r = idx >> 14;
    int n = (idx >> 7) & 127;
    int k = idx & 127;
    float v = (r < RR) ? Wrel[((size_t)r * DD + k) * DD + n]
                       : Wself[(size_t)n * DD + k];
    __nv_bfloat16 hb = __float2bfloat16(v);
    __nv_bfloat16 lb = __float2bfloat16(v - __bfloat162float(hb));
    int ui = chidx(n, k >> 3);
    int bo = ui * 16 + (k & 7) * 2;
    *(__nv_bfloat16*)((char*)(g_WbHi + (size_t)r * 2048) + bo) = hb;
    *(__nv_bfloat16*)((char*)(g_WbLo + (size_t)r * 2048) + bo) = lb;
}

// ---------------------------------------------------------------------------
// Kernel 3: bf16 mma.sync GEMM, 3-pass hi/lo split, fp32 accumulators.
//   One CTA per 128-row tile; loops over 9 relations (B double-buffered
//   via cp.async). Warp tile 32x64: warp (wid&3) -> rows, (wid>>2) -> cols.
// ---------------------------------------------------------------------------
#define SMA_HI 0
#define SMA_LO 32768
#define SMB    65536
#define SMB_BUF 65536          // per buffer: hi 32KB + lo 32KB
#define SM_TOTAL (65536 + 2 * SMB_BUF)   // 192 KB

__device__ __forceinline__ void copyB(int r, int buf, int tid, char* smem) {
    uint32_t dh = smem_u32(smem + SMB + buf * SMB_BUF) + (uint32_t)tid * 16;
    uint32_t dl = dh + 32768;
    const uint4* sh = g_WbHi + (size_t)r * 2048 + tid;
    const uint4* sl = g_WbLo + (size_t)r * 2048 + tid;
    #pragma unroll
    for (int i = 0; i < 8; i++) {
        asm volatile("cp.async.cg.shared.global [%0], [%1], 16;"
                     :: "r"(dh + i * 4096), "l"(sh + i * 256));
        asm volatile("cp.async.cg.shared.global [%0], [%1], 16;"
                     :: "r"(dl + i * 4096), "l"(sl + i * 256));
    }
    asm volatile("cp.async.commit_group;" ::: "memory");
}

__global__ void __launch_bounds__(256, 1) gemm_mma(const float* __restrict__ x) {
    extern __shared__ char smem[];
    uint4* sAhi = (uint4*)(smem + SMA_HI);
    uint4* sAlo = (uint4*)(smem + SMA_LO);
    const int tid = threadIdx.x, wid = tid >> 5, lane = tid & 31;
    const int m0 = blockIdx.x * 128;

    // --- convert x tile -> A hi/lo (bf16, swizzled) ---
    {
        int row = tid >> 1, half = tid & 1;
        int m = m0 + row;
        bool ok = m < NN;
        const float4* xr = (const float4*)(x + (size_t)m * DD);
        #pragma unroll
        for (int j = 0; j < 8; j++) {
            int cc = half * 8 + j;
            float4 f0 = ok ? __ldg(xr + cc * 2)     : make_float4(0, 0, 0, 0);
            float4 f1 = ok ? __ldg(xr + cc * 2 + 1) : make_float4(0, 0, 0, 0);
            float f[8] = {f0.x, f0.y, f0.z, f0.w, f1.x, f1.y, f1.z, f1.w};
            uint32_t uh[4], ul[4];
            #pragma unroll
            for (int q = 0; q < 4; q++) {
                __nv_bfloat16 h0 = __float2bfloat16(f[2 * q]);
                __nv_bfloat16 h1 = __float2bfloat16(f[2 * q + 1]);
                __nv_bfloat16 l0 = __float2bfloat16(f[2 * q]     - __bfloat162float(h0));
                __nv_bfloat16 l1 = __float2bfloat16(f[2 * q + 1] - __bfloat162float(h1));
                __nv_bfloat162 ph; ph.x = h0; ph.y = h1;
                __nv_bfloat162 pl; pl.x = l0; pl.y = l1;
                uh[q] = *(uint32_t*)&ph;
                ul[q] = *(uint32_t*)&pl;
            }
            int ui = chidx(row, cc);
            sAhi[ui] = make_uint4(uh[0], uh[1], uh[2], uh[3]);
            sAlo[ui] = make_uint4(ul[0], ul[1], ul[2], ul[3]);
        }
    }

    copyB(0, 0, tid, smem);   // prefetch B[0]

    const int mw = (wid & 3) * 32;
    const int nw = (wid >> 2) * 64;
    float acc[2][8][4];
    #pragma unroll
    for (int t = 0; t < 2; t++)
        #pragma unroll
        for (int j = 0; j < 8; j++)
            #pragma unroll
            for (int q = 0; q < 4; q++) acc[t][j][q] = 0.0f;

    __syncthreads();   // A visible to all warps

    for (int r = 0; r < NREL; r++) {
        int buf = r & 1;
        if (r + 1 < NREL) {
            copyB(r + 1, buf ^ 1, tid, smem);
            asm volatile("cp.async.wait_group 1;" ::: "memory");
        } else {
            asm volatile("cp.async.wait_group 0;" ::: "memory");
        }
        __syncthreads();

        const uint4* bh = (const uint4*)(smem + SMB + buf * SMB_BUF);
        const uint4* bl = bh + 2048;

        #pragma unroll
        for (int p = 0; p < 3; p++) {
            const uint4* As = (p == 2) ? sAlo : sAhi;
            const uint4* Bs = (p == 1) ? bl : bh;
            #pragma unroll
            for (int ks = 0; ks < 8; ks++) {
                uint32_t a[2][4];
                #pragma unroll
                for (int t = 0; t < 2; t++) {
                    int row = mw + t * 16 + (lane & 15);
                    int cc  = 2 * ks + (lane >> 4);
                    ldsm_x4(a[t], smem_u32(&As[chidx(row, cc)]));
                }
                #pragma unroll
                for (int j = 0; j < 8; j++) {
                    uint32_t b[2];
                    int nrow = nw + j * 8 + (lane & 7);
                    int cc   = 2 * ks + ((lane >> 3) & 1);
                    ldsm_x2(b, smem_u32(&Bs[chidx(nrow, cc)]));
                    mma16816(acc[0][j], a[0], b);
                    mma16816(acc[1][j], a[1], b);
                }
            }
        }

        // --- store tile to g_h[r], reset acc ---
        {
            int gid = lane >> 2, tig = lane & 3;
            float* hb2 = g_h + (size_t)r * NN * DD;
            #pragma unroll
            for (int t = 0; t < 2; t++) {
                #pragma unroll
                for (int j = 0; j < 8; j++) {
                    int rr0 = m0 + mw + t * 16 + gid;
                    int col = nw + j * 8 + tig * 2;
                    if (rr0 < NN)
                        *(float2*)(hb2 + (size_t)rr0 * DD + col) =
                            make_float2(acc[t][j][0], acc[t][j][1]);
                    int rr1 = rr0 + 8;
                    if (rr1 < NN)
                        *(float2*)(hb2 + (size_t)rr1 * DD + col) =
                            make_float2(acc[t][j][2], acc[t][j][3]);
                    acc[t][j][0] = acc[t][j][1] = acc[t][j][2] = acc[t][j][3] = 0.0f;
                }
            }
        }
        __syncthreads();   // everyone done with this B buffer before it is refilled
    }
}

// ---------------------------------------------------------------------------
// Kernel 4: edge gather + scatter-add (one warp per edge, vector RED)
// ---------------------------------------------------------------------------
__global__ __launch_bounds__(256) void edge_kernel(const int* __restrict__ ei,
                                                   const int* __restrict__ et) {
    int widx = (int)(((size_t)blockIdx.x * blockDim.x + threadIdx.x) >> 5);
    int lane = threadIdx.x & 31;
    if (widx >= EE) return;

    int s = __ldg(ei + widx);
    int d = __ldg(ei + EE + widx);
    int r = __ldg(et + widx);

    const float4* hrow = (const float4*)(g_h + ((size_t)r * NN + s) * DD);
    float4 v = __ldg(hrow + lane);

    float* a = g_agg + (size_t)d * DD + lane * 4;
    asm volatile("red.global.add.v4.f32 [%0], {%1, %2, %3, %4};"
                 :: "l"(a), "f"(v.x), "f"(v.y), "f"(v.z), "f"(v.w) : "memory");

    if (lane == 0) atomicAdd(&g_deg[d], 1);
}

// ---------------------------------------------------------------------------
// Kernel 5: out = relu(h_self + bias + agg/deg)
// ---------------------------------------------------------------------------
__global__ __launch_bounds__(256) void final_ep(const float* __restrict__ bias,
                                                float* __restrict__ out) {
    int i = blockIdx.x * 256 + threadIdx.x;       // over NN*32 float4s
    if (i >= NN * (DD / 4)) return;
    int m = i >> 5;
    int c4 = (i & 31) * 4;
    int dg = g_deg[m];
    float inv = 1.0f / (float)(dg > 1 ? dg : 1);
    float4 hs = *(const float4*)(g_h + (size_t)RR * NN * DD + (size_t)i * 4);
    float4 ag = *(const float4*)(g_agg + (size_t)i * 4);
    float4 b  = *(const float4*)(bias + c4);
    float4 o;
    o.x = fmaxf(hs.x + b.x + ag.x * inv, 0.0f);
    o.y = fmaxf(hs.y + b.y + ag.y * inv, 0.0f);
    o.z = fmaxf(hs.z + b.z + ag.z * inv, 0.0f);
    o.w = fmaxf(hs.w + b.w + ag.w * inv, 0.0f);
    *(float4*)(out + (size_t)i * 4) = o;
}

// ---------------------------------------------------------------------------
extern "C" void kernel_launch(void* const* d_in, const int* in_sizes, int n_in,
                              void* d_out, int out_size) {
    const float* x     = (const float*)d_in[0];
    const float* Wrel  = (const float*)d_in[1];
    const float* Wself = (const float*)d_in[2];
    const float* bias  = (const float*)d_in[3];
    const int*   ei    = (const int*)d_in[4];
    const int*   et    = (const int*)d_in[5];
    float* out = (float*)d_out;
    (void)in_sizes; (void)n_in; (void)out_size;

    cudaFuncSetAttribute(gemm_mma, cudaFuncAttributeMaxDynamicSharedMemorySize, SM_TOTAL);

    zero_kernel<<<(NN * DD + 255) / 256, 256>>>();
    prep_w<<<(NREL * DD * DD + 255) / 256, 256>>>(Wrel, Wself);
    gemm_mma<<<MTILES, 256, SM_TOTAL>>>(x);
    edge_kernel<<<(int)(((size_t)EE * 32 + 255) / 256), 256>>>(ei, et);
    final_ep<<<(NN * (DD / 4) + 255) / 256, 256>>>(bias, out);
}

// round 4
// speedup vs baseline: 2.1999x; 1.0488x over previous
#include <cuda_runtime.h>
#include <cuda_bf16.h>
#include <cuda_fp16.h>
#include <cstdint>

#define NN 50000
#define EE 800000
#define RR 8
#define DD 128
#define NREL 9              // 8 relations + self-loop as relation 8
#define MTILES 391          // ceil(50000/128)

// ---------------------------------------------------------------------------
// Device scratch (no runtime allocation allowed)
// ---------------------------------------------------------------------------
__device__ __half g_h[(size_t)NREL * NN * DD]; // 115.2 MB (fp16) -> ~L2-resident
__device__ float  g_agg[(size_t)NN * DD];      // 25.6 MB fp32 scatter target
__device__ int    g_deg[NN];
// Pre-split weights, bf16 hi/lo, already in the swizzled [row][chunk] smem image
__device__ uint4  g_WbHi[NREL * 2048];         // 32 KB / relation
__device__ uint4  g_WbLo[NREL * 2048];

// ---------------------------------------------------------------------------
__device__ __forceinline__ uint32_t smem_u32(const void* p) {
    return (uint32_t)__cvta_generic_to_shared(p);
}
// row in [0,128), cc = 16B-chunk in [0,16). XOR swizzle on low 3 chunk bits.
__device__ __forceinline__ int chidx(int row, int cc) {
    return row * 16 + ((cc & 8) | ((cc ^ row) & 7));
}

__device__ __forceinline__ void ldsm_x4(uint32_t* d, uint32_t addr) {
    asm volatile("ldmatrix.sync.aligned.m8n8.x4.shared.b16 {%0,%1,%2,%3}, [%4];"
                 : "=r"(d[0]), "=r"(d[1]), "=r"(d[2]), "=r"(d[3]) : "r"(addr));
}
__device__ __forceinline__ void mma16816(float* c, const uint32_t* a, const uint32_t* b) {
    asm volatile("mma.sync.aligned.m16n8k16.row.col.f32.bf16.bf16.f32 "
                 "{%0,%1,%2,%3}, {%4,%5,%6,%7}, {%8,%9}, {%0,%1,%2,%3};"
                 : "+f"(c[0]), "+f"(c[1]), "+f"(c[2]), "+f"(c[3])
                 : "r"(a[0]), "r"(a[1]), "r"(a[2]), "r"(a[3]), "r"(b[0]), "r"(b[1]));
}

// ---------------------------------------------------------------------------
// Kernel 1: zero agg + deg
// ---------------------------------------------------------------------------
__global__ void zero_kernel() {
    size_t i = (size_t)blockIdx.x * blockDim.x + threadIdx.x;
    if (i < (size_t)NN * DD) g_agg[i] = 0.0f;
    if (i < NN) g_deg[i] = 0;
}

// ---------------------------------------------------------------------------
// Kernel 2: pack weights -> bf16 hi/lo, swizzled [n-row][k-chunk] layout.
//   B[n][k]:  r<8:  W_rel[r][k][n]   (h = x @ W_rel[r])
//             r==8: W_self_w[n][k]   (x @ W_self^T)
// ---------------------------------------------------------------------------
__global__ void prep_w(const float* __restrict__ Wrel, const float* __restrict__ Wself) {
    int idx = blockIdx.x * 256 + threadIdx.x;
    if (idx >= NREL * DD * DD) return;
    int r = idx >> 14;
    int n = (idx >> 7) & 127;
    int k = idx & 127;
    float v = (r < RR) ? Wrel[((size_t)r * DD + k) * DD + n]
                       : Wself[(size_t)n * DD + k];
    __nv_bfloat16 hb = __float2bfloat16(v);
    __nv_bfloat16 lb = __float2bfloat16(v - __bfloat162float(hb));
    int ui = chidx(n, k >> 3);
    int bo = ui * 16 + (k & 7) * 2;
    *(__nv_bfloat16*)((char*)(g_WbHi + (size_t)r * 2048) + bo) = hb;
    *(__nv_bfloat16*)((char*)(g_WbLo + (size_t)r * 2048) + bo) = lb;
}

// ---------------------------------------------------------------------------
// Kernel 3: bf16 mma.sync GEMM, 3-pass hi/lo split, fp32 acc, fp16 output.
// ---------------------------------------------------------------------------
#define SMA_HI 0
#define SMA_LO 32768
#define SMB    65536
#define SMB_BUF 65536          // per buffer: hi 32KB + lo 32KB
#define SM_TOTAL (65536 + 2 * SMB_BUF)   // 192 KB

__device__ __forceinline__ void copyB(int r, int buf, int tid, char* smem) {
    uint32_t dh = smem_u32(smem + SMB + buf * SMB_BUF) + (uint32_t)tid * 16;
    uint32_t dl = dh + 32768;
    const uint4* sh = g_WbHi + (size_t)r * 2048 + tid;
    const uint4* sl = g_WbLo + (size_t)r * 2048 + tid;
    #pragma unroll
    for (int i = 0; i < 8; i++) {
        asm volatile("cp.async.cg.shared.global [%0], [%1], 16;"
                     :: "r"(dh + i * 4096), "l"(sh + i * 256));
        asm volatile("cp.async.cg.shared.global [%0], [%1], 16;"
                     :: "r"(dl + i * 4096), "l"(sl + i * 256));
    }
    asm volatile("cp.async.commit_group;" ::: "memory");
}

__global__ void __launch_bounds__(256, 1) gemm_mma(const float* __restrict__ x) {
    extern __shared__ char smem[];
    uint4* sAhi = (uint4*)(smem + SMA_HI);
    uint4* sAlo = (uint4*)(smem + SMA_LO);
    const int tid = threadIdx.x, wid = tid >> 5, lane = tid & 31;
    const int m0 = blockIdx.x * 128;

    // --- convert x tile -> A hi/lo (bf16, swizzled) ---
    {
        int row = tid >> 1, half = tid & 1;
        int m = m0 + row;
        bool ok = m < NN;
        const float4* xr = (const float4*)(x + (size_t)m * DD);
        #pragma unroll
        for (int j = 0; j < 8; j++) {
            int cc = half * 8 + j;
            float4 f0 = ok ? __ldg(xr + cc * 2)     : make_float4(0, 0, 0, 0);
            float4 f1 = ok ? __ldg(xr + cc * 2 + 1) : make_float4(0, 0, 0, 0);
            float f[8] = {f0.x, f0.y, f0.z, f0.w, f1.x, f1.y, f1.z, f1.w};
            uint32_t uh[4], ul[4];
            #pragma unroll
            for (int q = 0; q < 4; q++) {
                __nv_bfloat16 h0 = __float2bfloat16(f[2 * q]);
                __nv_bfloat16 h1 = __float2bfloat16(f[2 * q + 1]);
                __nv_bfloat16 l0 = __float2bfloat16(f[2 * q]     - __bfloat162float(h0));
                __nv_bfloat16 l1 = __float2bfloat16(f[2 * q + 1] - __bfloat162float(h1));
                __nv_bfloat162 ph; ph.x = h0; ph.y = h1;
                __nv_bfloat162 pl; pl.x = l0; pl.y = l1;
                uh[q] = *(uint32_t*)&ph;
                ul[q] = *(uint32_t*)&pl;
            }
            int ui = chidx(row, cc);
            sAhi[ui] = make_uint4(uh[0], uh[1], uh[2], uh[3]);
            sAlo[ui] = make_uint4(ul[0], ul[1], ul[2], ul[3]);
        }
    }

    copyB(0, 0, tid, smem);   // prefetch B[0]

    const int mw = (wid & 3) * 32;
    const int nw = (wid >> 2) * 64;
    float acc[2][8][4];
    #pragma unroll
    for (int t = 0; t < 2; t++)
        #pragma unroll
        for (int j = 0; j < 8; j++)
            #pragma unroll
            for (int q = 0; q < 4; q++) acc[t][j][q] = 0.0f;

    __syncthreads();   // A visible to all warps

    for (int r = 0; r < NREL; r++) {
        int buf = r & 1;
        if (r + 1 < NREL) {
            copyB(r + 1, buf ^ 1, tid, smem);
            asm volatile("cp.async.wait_group 1;" ::: "memory");
        } else {
            asm volatile("cp.async.wait_group 0;" ::: "memory");
        }
        __syncthreads();

        const uint4* bh = (const uint4*)(smem + SMB + buf * SMB_BUF);
        const uint4* bl = bh + 2048;

        #pragma unroll
        for (int p = 0; p < 3; p++) {
            const uint4* As = (p == 2) ? sAlo : sAhi;
            const uint4* Bs = (p == 1) ? bl : bh;
            #pragma unroll
            for (int ks = 0; ks < 8; ks++) {
                uint32_t a[2][4];
                #pragma unroll
                for (int t = 0; t < 2; t++) {
                    int row = mw + t * 16 + (lane & 15);
                    int cc  = 2 * ks + (lane >> 4);
                    ldsm_x4(a[t], smem_u32(&As[chidx(row, cc)]));
                }
                #pragma unroll
                for (int j2 = 0; j2 < 4; j2++) {
                    // x4 B load: two n8 fragments (j = 2*j2, 2*j2+1)
                    uint32_t b4[4];
                    int q   = lane >> 3;               // matrix id 0..3
                    int row = nw + j2 * 16 + (q >> 1) * 8 + (lane & 7);
                    int cc  = 2 * ks + (q & 1);
                    ldsm_x4(b4, smem_u32(&Bs[chidx(row, cc)]));
                    mma16816(acc[0][2 * j2],     a[0], b4);
                    mma16816(acc[1][2 * j2],     a[1], b4);
                    mma16816(acc[0][2 * j2 + 1], a[0], b4 + 2);
                    mma16816(acc[1][2 * j2 + 1], a[1], b4 + 2);
                }
            }
        }

        // --- store tile to g_h[r] as fp16, reset acc ---
        {
            int gid = lane >> 2, tig = lane & 3;
            __half* hb2 = g_h + (size_t)r * NN * DD;
            #pragma unroll
            for (int t = 0; t < 2; t++) {
                #pragma unroll
                for (int j = 0; j < 8; j++) {
                    int rr0 = m0 + mw + t * 16 + gid;
                    int col = nw + j * 8 + tig * 2;
                    if (rr0 < NN)
                        *(__half2*)(hb2 + (size_t)rr0 * DD + col) =
                            __floats2half2_rn(acc[t][j][0], acc[t][j][1]);
                    int rr1 = rr0 + 8;
                    if (rr1 < NN)
                        *(__half2*)(hb2 + (size_t)rr1 * DD + col) =
                            __floats2half2_rn(acc[t][j][2], acc[t][j][3]);
                    acc[t][j][0] = acc[t][j][1] = acc[t][j][2] = acc[t][j][3] = 0.0f;
                }
            }
        }
        __syncthreads();   // everyone done with this B buffer before it is refilled
    }
}

// ---------------------------------------------------------------------------
// Kernel 4: edge gather + scatter-add (one warp per edge, vector RED)
//   fp16 gather (256B/row, uint2 per lane) -> fp32 vec4 RED
// ---------------------------------------------------------------------------
__global__ __launch_bounds__(256) void edge_kernel(const int* __restrict__ ei,
                                                   const int* __restrict__ et) {
    int widx = (int)(((size_t)blockIdx.x * blockDim.x + threadIdx.x) >> 5);
    int lane = threadIdx.x & 31;
    if (widx >= EE) return;

    int s = __ldg(ei + widx);
    int d = __ldg(ei + EE + widx);
    int r = __ldg(et + widx);

    const uint2* hrow = (const uint2*)(g_h + ((size_t)r * NN + s) * DD);
    uint2 pv = __ldg(hrow + lane);
    __half2 h0 = *reinterpret_cast<__half2*>(&pv.x);
    __half2 h1 = *reinterpret_cast<__half2*>(&pv.y);
    float2 f0 = __half22float2(h0);
    float2 f1 = __half22float2(h1);

    float* a = g_agg + (size_t)d * DD + lane * 4;
    asm volatile("red.global.add.v4.f32 [%0], {%1, %2, %3, %4};"
                 :: "l"(a), "f"(f0.x), "f"(f0.y), "f"(f1.x), "f"(f1.y) : "memory");

    if (lane == 0) atomicAdd(&g_deg[d], 1);
}

// ---------------------------------------------------------------------------
// Kernel 5: out = relu(h_self + bias + agg/deg)
// ---------------------------------------------------------------------------
__global__ __launch_bounds__(256) void final_ep(const float* __restrict__ bias,
                                                float* __restrict__ out) {
    int i = blockIdx.x * 256 + threadIdx.x;       // over NN*32 float4s
    if (i >= NN * (DD / 4)) return;
    int m = i >> 5;
    int c4 = (i & 31) * 4;
    int dg = g_deg[m];
    float inv = 1.0f / (float)(dg > 1 ? dg : 1);
    const __half2* hsp = (const __half2*)(g_h + (size_t)RR * NN * DD + (size_t)i * 4);
    float2 hs0 = __half22float2(hsp[0]);
    float2 hs1 = __half22float2(hsp[1]);
    float4 ag = *(const float4*)(g_agg + (size_t)i * 4);
    float4 b  = *(const float4*)(bias + c4);
    float4 o;
    o.x = fmaxf(hs0.x + b.x + ag.x * inv, 0.0f);
    o.y = fmaxf(hs0.y + b.y + ag.y * inv, 0.0f);
    o.z = fmaxf(hs1.x + b.z + ag.z * inv, 0.0f);
    o.w = fmaxf(hs1.y + b.w + ag.w * inv, 0.0f);
    *(float4*)(out + (size_t)i * 4) = o;
}

// ---------------------------------------------------------------------------
extern "C" void kernel_launch(void* const* d_in, const int* in_sizes, int n_in,
                              void* d_out, int out_size) {
    const float* x     = (const float*)d_in[0];
    const float* Wrel  = (const float*)d_in[1];
    const float* Wself = (const float*)d_in[2];
    const float* bias  = (const float*)d_in[3];
    const int*   ei    = (const int*)d_in[4];
    const int*   et    = (const int*)d_in[5];
    float* out = (float*)d_out;
    (void)in_sizes; (void)n_in; (void)out_size;

    cudaFuncSetAttribute(gemm_mma, cudaFuncAttributeMaxDynamicSharedMemorySize, SM_TOTAL);

    zero_kernel<<<(NN * DD + 255) / 256, 256>>>();
    prep_w<<<(NREL * DD * DD + 255) / 256, 256>>>(Wrel, Wself);
    gemm_mma<<<MTILES, 256, SM_TOTAL>>>(x);
    edge_kernel<<<(int)(((size_t)EE * 32 + 255) / 256), 256>>>(ei, et);
    final_ep<<<(NN * (DD / 4) + 255) / 256, 256>>>(bias, out);
}

// round 5
// speedup vs baseline: 2.8017x; 1.2735x over previous
#include <cuda_runtime.h>
#include <cuda_bf16.h>
#include <cuda_fp16.h>
#include <cstdint>

#define NN 50000
#define EE 800000
#define RR 8
#define DD 128
#define NREL 9              // 8 relations + self-loop as relation 8
#define MTILES 391          // ceil(50000/128)
#define SCAN_BLK 512
#define NBLK 98             // ceil(50000/512)

// ---------------------------------------------------------------------------
// Device scratch (no runtime allocation allowed)
// ---------------------------------------------------------------------------
__device__ __half   g_h[(size_t)NREL * NN * DD]; // 115.2 MB fp16, ~L2-resident
__device__ int      g_cnt[NN];                   // per-dst degree (histogram)
__device__ int      g_off[NN + 1];               // CSR offsets
__device__ int      g_cur[NN];                   // scatter cursors
__device__ int      g_bsum[NBLK + 32];           // scan block sums
__device__ int      g_bsum2[NBLK + 32];
__device__ uint32_t g_srcrel[EE];                // packed src | (rel<<16), dst-sorted
// Pre-split weights, bf16 hi/lo, swizzled smem image
__device__ uint4    g_WbHi[NREL * 2048];
__device__ uint4    g_WbLo[NREL * 2048];

// ---------------------------------------------------------------------------
__device__ __forceinline__ uint32_t smem_u32(const void* p) {
    return (uint32_t)__cvta_generic_to_shared(p);
}
__device__ __forceinline__ int chidx(int row, int cc) {
    return row * 16 + ((cc & 8) | ((cc ^ row) & 7));
}
__device__ __forceinline__ void ldsm_x4(uint32_t* d, uint32_t addr) {
    asm volatile("ldmatrix.sync.aligned.m8n8.x4.shared.b16 {%0,%1,%2,%3}, [%4];"
                 : "=r"(d[0]), "=r"(d[1]), "=r"(d[2]), "=r"(d[3]) : "r"(addr));
}
__device__ __forceinline__ void mma16816(float* c, const uint32_t* a, const uint32_t* b) {
    asm volatile("mma.sync.aligned.m16n8k16.row.col.f32.bf16.bf16.f32 "
                 "{%0,%1,%2,%3}, {%4,%5,%6,%7}, {%8,%9}, {%0,%1,%2,%3};"
                 : "+f"(c[0]), "+f"(c[1]), "+f"(c[2]), "+f"(c[3])
                 : "r"(a[0]), "r"(a[1]), "r"(a[2]), "r"(a[3]), "r"(b[0]), "r"(b[1]));
}

// ---------------------------------------------------------------------------
// CSR build: zero -> hist -> scanA/B/C -> scatter
// ---------------------------------------------------------------------------
__global__ void zero_kernel() {
    int i = blockIdx.x * 256 + threadIdx.x;
    if (i < NN) { g_cnt[i] = 0; g_cur[i] = 0; }
}

__global__ void hist_kernel(const int* __restrict__ ei) {
    int e = blockIdx.x * 256 + threadIdx.x;
    if (e < EE) atomicAdd(&g_cnt[__ldg(ei + EE + e)], 1);
}

__global__ void scanA() {
    __shared__ int sd[SCAN_BLK];
    int t = threadIdx.x;
    int i = blockIdx.x * SCAN_BLK + t;
    int v = (i < NN) ? g_cnt[i] : 0;
    sd[t] = v; __syncthreads();
    #pragma unroll
    for (int s = 1; s < SCAN_BLK; s <<= 1) {
        int tmp = (t >= s) ? sd[t - s] : 0;
        __syncthreads();
        sd[t] += tmp;
        __syncthreads();
    }
    if (i < NN) g_off[i] = sd[t] - v;                 // exclusive partial
    if (t == SCAN_BLK - 1) g_bsum[blockIdx.x] = sd[t];
}

__global__ void scanB() {
    __shared__ int sd[128];
    int t = threadIdx.x;
    int v = (t < NBLK) ? g_bsum[t] : 0;
    sd[t] = v; __syncthreads();
    #pragma unroll
    for (int s = 1; s < 128; s <<= 1) {
        int tmp = (t >= s) ? sd[t - s] : 0;
        __syncthreads();
        sd[t] += tmp;
        __syncthreads();
    }
    if (t < NBLK) g_bsum2[t] = sd[t] - v;             // exclusive
}

__global__ void scanC() {
    int i = blockIdx.x * 256 + threadIdx.x;
    if (i < NN) g_off[i] += g_bsum2[i / SCAN_BLK];
    if (i == 0) g_off[NN] = EE;
}

__global__ void scatter_kernel(const int* __restrict__ ei, const int* __restrict__ et) {
    int e = blockIdx.x * 256 + threadIdx.x;
    if (e >= EE) return;
    int s = __ldg(ei + e);
    int d = __ldg(ei + EE + e);
    int r = __ldg(et + e);
    int pos = g_off[d] + atomicAdd(&g_cur[d], 1);
    g_srcrel[pos] = (uint32_t)s | ((uint32_t)r << 16);
}

// ---------------------------------------------------------------------------
// Pack weights -> bf16 hi/lo, swizzled [n-row][k-chunk] layout.
// ---------------------------------------------------------------------------
__global__ void prep_w(const float* __restrict__ Wrel, const float* __restrict__ Wself) {
    int idx = blockIdx.x * 256 + threadIdx.x;
    if (idx >= NREL * DD * DD) return;
    int r = idx >> 14;
    int n = (idx >> 7) & 127;
    int k = idx & 127;
    float v = (r < RR) ? Wrel[((size_t)r * DD + k) * DD + n]
                       : Wself[(size_t)n * DD + k];
    __nv_bfloat16 hb = __float2bfloat16(v);
    __nv_bfloat16 lb = __float2bfloat16(v - __bfloat162float(hb));
    int ui = chidx(n, k >> 3);
    int bo = ui * 16 + (k & 7) * 2;
    *(__nv_bfloat16*)((char*)(g_WbHi + (size_t)r * 2048) + bo) = hb;
    *(__nv_bfloat16*)((char*)(g_WbLo + (size_t)r * 2048) + bo) = lb;
}

// ---------------------------------------------------------------------------
// bf16 mma.sync GEMM, 3-pass hi/lo split, fp32 acc, fp16 output. (unchanged)
// ---------------------------------------------------------------------------
#define SMA_HI 0
#define SMA_LO 32768
#define SMB    65536
#define SMB_BUF 65536
#define SM_TOTAL (65536 + 2 * SMB_BUF)   // 192 KB

__device__ __forceinline__ void copyB(int r, int buf, int tid, char* smem) {
    uint32_t dh = smem_u32(smem + SMB + buf * SMB_BUF) + (uint32_t)tid * 16;
    uint32_t dl = dh + 32768;
    const uint4* sh = g_WbHi + (size_t)r * 2048 + tid;
    const uint4* sl = g_WbLo + (size_t)r * 2048 + tid;
    #pragma unroll
    for (int i = 0; i < 8; i++) {
        asm volatile("cp.async.cg.shared.global [%0], [%1], 16;"
                     :: "r"(dh + i * 4096), "l"(sh + i * 256));
        asm volatile("cp.async.cg.shared.global [%0], [%1], 16;"
                     :: "r"(dl + i * 4096), "l"(sl + i * 256));
    }
    asm volatile("cp.async.commit_group;" ::: "memory");
}

__global__ void __launch_bounds__(256, 1) gemm_mma(const float* __restrict__ x) {
    extern __shared__ char smem[];
    uint4* sAhi = (uint4*)(smem + SMA_HI);
    uint4* sAlo = (uint4*)(smem + SMA_LO);
    const int tid = threadIdx.x, wid = tid >> 5, lane = tid & 31;
    const int m0 = blockIdx.x * 128;

    // --- convert x tile -> A hi/lo (bf16, swizzled) ---
    {
        int row = tid >> 1, half = tid & 1;
        int m = m0 + row;
        bool ok = m < NN;
        const float4* xr = (const float4*)(x + (size_t)m * DD);
        #pragma unroll
        for (int j = 0; j < 8; j++) {
            int cc = half * 8 + j;
            float4 f0 = ok ? __ldg(xr + cc * 2)     : make_float4(0, 0, 0, 0);
            float4 f1 = ok ? __ldg(xr + cc * 2 + 1) : make_float4(0, 0, 0, 0);
            float f[8] = {f0.x, f0.y, f0.z, f0.w, f1.x, f1.y, f1.z, f1.w};
            uint32_t uh[4], ul[4];
            #pragma unroll
            for (int q = 0; q < 4; q++) {
                __nv_bfloat16 h0 = __float2bfloat16(f[2 * q]);
                __nv_bfloat16 h1 = __float2bfloat16(f[2 * q + 1]);
                __nv_bfloat16 l0 = __float2bfloat16(f[2 * q]     - __bfloat162float(h0));
                __nv_bfloat16 l1 = __float2bfloat16(f[2 * q + 1] - __bfloat162float(h1));
                __nv_bfloat162 ph; ph.x = h0; ph.y = h1;
                __nv_bfloat162 pl; pl.x = l0; pl.y = l1;
                uh[q] = *(uint32_t*)&ph;
                ul[q] = *(uint32_t*)&pl;
            }
            int ui = chidx(row, cc);
            sAhi[ui] = make_uint4(uh[0], uh[1], uh[2], uh[3]);
            sAlo[ui] = make_uint4(ul[0], ul[1], ul[2], ul[3]);
        }
    }

    copyB(0, 0, tid, smem);

    const int mw = (wid & 3) * 32;
    const int nw = (wid >> 2) * 64;
    float acc[2][8][4];
    #pragma unroll
    for (int t = 0; t < 2; t++)
        #pragma unroll
        for (int j = 0; j < 8; j++)
            #pragma unroll
            for (int q = 0; q < 4; q++) acc[t][j][q] = 0.0f;

    __syncthreads();

    for (int r = 0; r < NREL; r++) {
        int buf = r & 1;
        if (r + 1 < NREL) {
            copyB(r + 1, buf ^ 1, tid, smem);
            asm volatile("cp.async.wait_group 1;" ::: "memory");
        } else {
            asm volatile("cp.async.wait_group 0;" ::: "memory");
        }
        __syncthreads();

        const uint4* bh = (const uint4*)(smem + SMB + buf * SMB_BUF);
        const uint4* bl = bh + 2048;

        #pragma unroll
        for (int p = 0; p < 3; p++) {
            const uint4* As = (p == 2) ? sAlo : sAhi;
            const uint4* Bs = (p == 1) ? bl : bh;
            #pragma unroll
            for (int ks = 0; ks < 8; ks++) {
                uint32_t a[2][4];
                #pragma unroll
                for (int t = 0; t < 2; t++) {
                    int row = mw + t * 16 + (lane & 15);
                    int cc  = 2 * ks + (lane >> 4);
                    ldsm_x4(a[t], smem_u32(&As[chidx(row, cc)]));
                }
                #pragma unroll
                for (int j2 = 0; j2 < 4; j2++) {
                    uint32_t b4[4];
                    int q   = lane >> 3;
                    int row = nw + j2 * 16 + (q >> 1) * 8 + (lane & 7);
                    int cc  = 2 * ks + (q & 1);
                    ldsm_x4(b4, smem_u32(&Bs[chidx(row, cc)]));
                    mma16816(acc[0][2 * j2],     a[0], b4);
                    mma16816(acc[1][2 * j2],     a[1], b4);
                    mma16816(acc[0][2 * j2 + 1], a[0], b4 + 2);
                    mma16816(acc[1][2 * j2 + 1], a[1], b4 + 2);
                }
            }
        }

        // --- store tile to g_h[r] as fp16, reset acc ---
        {
            int gid = lane >> 2, tig = lane & 3;
            __half* hb2 = g_h + (size_t)r * NN * DD;
            #pragma unroll
            for (int t = 0; t < 2; t++) {
                #pragma unroll
                for (int j = 0; j < 8; j++) {
                    int rr0 = m0 + mw + t * 16 + gid;
                    int col = nw + j * 8 + tig * 2;
                    if (rr0 < NN)
                        *(__half2*)(hb2 + (size_t)rr0 * DD + col) =
                            __floats2half2_rn(acc[t][j][0], acc[t][j][1]);
                    int rr1 = rr0 + 8;
                    if (rr1 < NN)
                        *(__half2*)(hb2 + (size_t)rr1 * DD + col) =
                            __floats2half2_rn(acc[t][j][2], acc[t][j][3]);
                    acc[t][j][0] = acc[t][j][1] = acc[t][j][2] = acc[t][j][3] = 0.0f;
                }
            }
        }
        __syncthreads();
    }
}

// ---------------------------------------------------------------------------
// Aggregation + epilogue (fused): one warp per dst node, NO atomics.
//   acc = sum over edges of h[rel][src]; out = relu(h_self + bias + acc/deg)
// ---------------------------------------------------------------------------
__device__ __forceinline__ void acc_row(float* acc, uint32_t e, int lane) {
    int s = (int)(e & 0xFFFF);
    int r = (int)(e >> 16);
    uint2 pv = __ldg((const uint2*)(g_h + ((size_t)r * NN + s) * DD) + lane);
    __half2 h0 = *reinterpret_cast<__half2*>(&pv.x);
    __half2 h1 = *reinterpret_cast<__half2*>(&pv.y);
    float2 f0 = __half22float2(h0);
    float2 f1 = __half22float2(h1);
    acc[0] += f0.x; acc[1] += f0.y; acc[2] += f1.x; acc[3] += f1.y;
}

__global__ void __launch_bounds__(256) agg_kernel(const float* __restrict__ bias,
                                                  float* __restrict__ out) {
    int m = (int)(((size_t)blockIdx.x * blockDim.x + threadIdx.x) >> 5);
    int lane = threadIdx.x & 31;
    if (m >= NN) return;

    int off = __ldg(&g_off[m]);
    int end = __ldg(&g_off[m + 1]);

    float acc[4] = {0.0f, 0.0f, 0.0f, 0.0f};
    for (int base = off; base < end; base += 32) {
        int n = end - base; if (n > 32) n = 32;
        uint32_t e = 0;
        if (base + lane < end) e = __ldg(&g_srcrel[base + lane]);
        int j = 0;
        for (; j + 4 <= n; j += 4) {
            uint32_t e0 = __shfl_sync(0xFFFFFFFFu, e, j);
            uint32_t e1 = __shfl_sync(0xFFFFFFFFu, e, j + 1);
            uint32_t e2 = __shfl_sync(0xFFFFFFFFu, e, j + 2);
            uint32_t e3 = __shfl_sync(0xFFFFFFFFu, e, j + 3);
            acc_row(acc, e0, lane);
            acc_row(acc, e1, lane);
            acc_row(acc, e2, lane);
            acc_row(acc, e3, lane);
        }
        for (; j < n; j++) {
            uint32_t ej = __shfl_sync(0xFFFFFFFFu, e, j);
            acc_row(acc, ej, lane);
        }
    }

    int deg = end - off;
    float inv = 1.0f / (float)(deg > 1 ? deg : 1);

    // self part + bias + relu
    uint2 pv = __ldg((const uint2*)(g_h + ((size_t)RR * NN + m) * DD) + lane);
    __half2 h0 = *reinterpret_cast<__half2*>(&pv.x);
    __half2 h1 = *reinterpret_cast<__half2*>(&pv.y);
    float2 s0 = __half22float2(h0);
    float2 s1 = __half22float2(h1);
    float4 b = __ldg((const float4*)(bias) + lane);

    float4 o;
    o.x = fmaxf(s0.x + b.x + acc[0] * inv, 0.0f);
    o.y = fmaxf(s0.y + b.y + acc[1] * inv, 0.0f);
    o.z = fmaxf(s1.x + b.z + acc[2] * inv, 0.0f);
    o.w = fmaxf(s1.y + b.w + acc[3] * inv, 0.0f);
    *((float4*)(out + (size_t)m * DD) + lane) = o;
}

// ---------------------------------------------------------------------------
extern "C" void kernel_launch(void* const* d_in, const int* in_sizes, int n_in,
                              void* d_out, int out_size) {
    const float* x     = (const float*)d_in[0];
    const float* Wrel  = (const float*)d_in[1];
    const float* Wself = (const float*)d_in[2];
    const float* bias  = (const float*)d_in[3];
    const int*   ei    = (const int*)d_in[4];
    const int*   et    = (const int*)d_in[5];
    float* out = (float*)d_out;
    (void)in_sizes; (void)n_in; (void)out_size;

    cudaFuncSetAttribute(gemm_mma, cudaFuncAttributeMaxDynamicSharedMemorySize, SM_TOTAL);

    zero_kernel<<<(NN + 255) / 256, 256>>>();
    prep_w<<<(NREL * DD * DD + 255) / 256, 256>>>(Wrel, Wself);
    hist_kernel<<<(EE + 255) / 256, 256>>>(ei);
    scanA<<<NBLK, SCAN_BLK>>>();
    scanB<<<1, 128>>>();
    scanC<<<(NN + 255) / 256, 256>>>();
    scatter_kernel<<<(EE + 255) / 256, 256>>>(ei, et);
    gemm_mma<<<MTILES, 256, SM_TOTAL>>>(x);
    agg_kernel<<<(int)(((size_t)NN * 32 + 255) / 256), 256>>>(bias, out);
}